// round 13
// baseline (speedup 1.0000x reference)
#include <cuda_runtime.h>
#include <cuda_fp16.h>
#include <cstdint>

#define VOCAB 100000
#define EMB   128

// Scratch: vocab-major, bias-fused, L2-normalized table in FP16.
// 100000 * 128 * 2B = 25.6 MB — firmly resident in GB300's ~126 MB L2.
__device__ __half g_table[(size_t)VOCAB * EMB];

// ---------------------------------------------------------------------------
// Kernel 1: table[v][:] = (half) normalize(W[:, v] + b)
// One block per 32 vocab entries, 256 threads. Vectorized LDG.128 loads.
// ---------------------------------------------------------------------------
__global__ __launch_bounds__(256) void build_table_kernel(
        const float* __restrict__ W,
        const float* __restrict__ b) {
    __shared__ float tile[EMB][33];   // [j][v_local], pad 33 -> conflict-free reduce

    const int v0   = blockIdx.x * 32;
    const int tid  = threadIdx.x;
    const int lane = tid & 31;
    const int wid  = tid >> 5;        // 0..7

    // ---- vectorized load + bias: 1024 float4 total, 4 per thread ----
    const float4* W4 = reinterpret_cast<const float4*>(W);
    const int row_f4 = VOCAB / 4;             // 25000 float4 per j-row
    const int base_c = blockIdx.x * 8;        // v0/4

    float4 f[4];
    int jj[4], cc[4];
    #pragma unroll
    for (int k = 0; k < 4; k++) {
        int q = tid + k * 256;
        jj[k] = q >> 3;                       // 0..127
        cc[k] = q & 7;                        // 0..7
        f[k] = __ldg(&W4[(size_t)jj[k] * row_f4 + base_c + cc[k]]);
    }
    #pragma unroll
    for (int k = 0; k < 4; k++) {
        const float bj = __ldg(&b[jj[k]]);
        float* dst = &tile[jj[k]][cc[k] * 4];
        dst[0] = f[k].x + bj;
        dst[1] = f[k].y + bj;
        dst[2] = f[k].z + bj;
        dst[3] = f[k].w + bj;
    }
    __syncthreads();

    // ---- each warp normalizes 4 vocab rows, writes half2 (coalesced) ----
    #pragma unroll
    for (int r = 0; r < 4; r++) {
        const int v = wid * 4 + r;

        float s = 0.f;
        #pragma unroll
        for (int k = 0; k < 4; k++) {
            float e = tile[lane + 32 * k][v];
            s += e * e;
        }
        #pragma unroll
        for (int o = 16; o > 0; o >>= 1)
            s += __shfl_xor_sync(0xFFFFFFFFu, s, o);

        const float inv = 1.0f / fmaxf(sqrtf(s), 1e-12f);

        __half2* dst = reinterpret_cast<__half2*>(g_table + (size_t)(v0 + v) * EMB);
        dst[lane]      = __floats2half2_rn(tile[2 * lane][v] * inv,
                                           tile[2 * lane + 1][v] * inv);
        dst[lane + 32] = __floats2half2_rn(tile[64 + 2 * lane][v] * inv,
                                           tile[64 + 2 * lane + 1][v] * inv);
    }
}

// ---------------------------------------------------------------------------
// 256-bit streaming store: 8 x b32 regs -> 32 bytes (Blackwell STG.256).
// ---------------------------------------------------------------------------
__device__ __forceinline__ void stg256_cs(float* p, const uint32_t* r) {
    asm volatile(
        "st.global.cs.v8.b32 [%0], {%1,%2,%3,%4,%5,%6,%7,%8};"
        :: "l"(p), "r"(r[0]), "r"(r[1]), "r"(r[2]), "r"(r[3]),
           "r"(r[4]), "r"(r[5]), "r"(r[6]), "r"(r[7])
        : "memory");
}

// ---------------------------------------------------------------------------
// Kernel 2: gather-copy + fp16->fp32 widen, half-warp per token.
// Warp handles 8 tokens as 4 pairs: lanes 0-15 -> token 2p, lanes 16-31 ->
// token 2p+1. Each lane does ONE LDG.128 (uint4 = 8 halves = 32B of output)
// and ONE STG.256 (8 floats, evict-first). Per token: 256B coalesced read,
// 512B coalesced write — half the L1tex wavefronts of the uint2/float4 form.
// ---------------------------------------------------------------------------
#define TOK_PER_WARP 8

__global__ __launch_bounds__(256) void gather_kernel(
        const int* __restrict__ x,
        float* __restrict__ out,
        int n_tok) {
    const int gwarp = (blockIdx.x * blockDim.x + threadIdx.x) >> 5;
    const int lane  = threadIdx.x & 31;
    const int t0    = gwarp * TOK_PER_WARP;
    if (t0 >= n_tok) return;

    const int half = lane >> 4;        // 0: token 2p, 1: token 2p+1
    const int sub  = lane & 15;        // uint4 index within the row

    if (t0 + TOK_PER_WARP <= n_tok) {
        int idx[TOK_PER_WARP];
        #pragma unroll
        for (int r = 0; r < TOK_PER_WARP; r++)
            idx[r] = __ldg(&x[t0 + r]);

        // Front-batched: 4 x LDG.128 in flight per lane.
        uint4 h[4];
        #pragma unroll
        for (int p = 0; p < 4; p++)
            h[p] = __ldg(reinterpret_cast<const uint4*>(
                       g_table + (size_t)idx[2 * p + half] * EMB) + sub);

        #pragma unroll
        for (int p = 0; p < 4; p++) {
            float2 f0 = __half22float2(*reinterpret_cast<__half2*>(&h[p].x));
            float2 f1 = __half22float2(*reinterpret_cast<__half2*>(&h[p].y));
            float2 f2 = __half22float2(*reinterpret_cast<__half2*>(&h[p].z));
            float2 f3 = __half22float2(*reinterpret_cast<__half2*>(&h[p].w));
            float v[8] = { f0.x, f0.y, f1.x, f1.y, f2.x, f2.y, f3.x, f3.y };
            stg256_cs(out + (size_t)(t0 + 2 * p + half) * EMB + sub * 8,
                      reinterpret_cast<const uint32_t*>(v));
        }
    } else {
        // Tail (unused for n_tok % 8 == 0): scalar-per-token fallback.
        for (int t = t0; t < n_tok; t++) {
            uint2 h = __ldg(reinterpret_cast<const uint2*>(
                          g_table + (size_t)__ldg(&x[t]) * EMB) + lane);
            float2 f0 = __half22float2(*reinterpret_cast<__half2*>(&h.x));
            float2 f1 = __half22float2(*reinterpret_cast<__half2*>(&h.y));
            float4 o;
            o.x = f0.x; o.y = f0.y; o.z = f1.x; o.w = f1.y;
            __stcs(reinterpret_cast<float4*>(out + (size_t)t * EMB) + lane, o);
        }
    }
}

// ---------------------------------------------------------------------------
extern "C" void kernel_launch(void* const* d_in, const int* in_sizes, int n_in,
                              void* d_out, int out_size) {
    const int*   x = (const int*)d_in[0];    // [4096, 200] int32
    const float* W = (const float*)d_in[1];  // [128, 100000] fp32
    const float* b = (const float*)d_in[2];  // [128] fp32
    float* out = (float*)d_out;              // [4096, 200, 128] fp32

    const int n_tok = in_sizes[0];           // 819200

    build_table_kernel<<<VOCAB / 32, 256>>>(W, b);

    const int warps_needed = (n_tok + TOK_PER_WARP - 1) / TOK_PER_WARP;  // 102400
    const int blocks = (warps_needed + 7) / 8;                            // 12800
    gather_kernel<<<blocks, 256>>>(x, out, n_tok);
}

// round 14
// speedup vs baseline: 1.1174x; 1.1174x over previous
#include <cuda_runtime.h>
#include <cuda_fp16.h>
#include <cstdint>

#define VOCAB 100000
#define EMB   128

// Scratch: vocab-major, bias-fused, L2-normalized table in FP16.
// 100000 * 128 * 2B = 25.6 MB — firmly resident in GB300's ~126 MB L2.
__device__ __half g_table[(size_t)VOCAB * EMB];

// ---------------------------------------------------------------------------
// Kernel 1: table[v][:] = (half) normalize(W[:, v] + b)
// One block per 32 vocab entries. Block = 256 threads.
// ---------------------------------------------------------------------------
__global__ __launch_bounds__(256) void build_table_kernel(
        const float* __restrict__ W,
        const float* __restrict__ b) {
    __shared__ float tile[EMB][33];   // [j][v_local], pad -> conflict-free reduce

    const int v0   = blockIdx.x * 32;
    const int tid  = threadIdx.x;
    const int lane = tid & 31;
    const int wid  = tid >> 5;        // 0..7

    // Load + bias: warp reads one j-row of 32 consecutive vocab cols (128B line).
    #pragma unroll
    for (int k = 0; k < 16; k++) {
        int j = k * 8 + wid;
        tile[j][lane] = W[(size_t)j * VOCAB + v0 + lane] + b[j];
    }
    __syncthreads();

    // Each warp normalizes 4 vocab rows and writes them as half2.
    #pragma unroll
    for (int r = 0; r < 4; r++) {
        const int v = wid * 4 + r;

        float s = 0.f;
        #pragma unroll
        for (int k = 0; k < 4; k++) {
            float e = tile[lane + 32 * k][v];
            s += e * e;
        }
        #pragma unroll
        for (int o = 16; o > 0; o >>= 1)
            s += __shfl_xor_sync(0xFFFFFFFFu, s, o);

        const float inv = 1.0f / fmaxf(sqrtf(s), 1e-12f);

        __half2* dst = reinterpret_cast<__half2*>(g_table + (size_t)(v0 + v) * EMB);
        // lane writes half2 pairs (2l, 2l+1) and (64+2l, 64+2l+1): coalesced 128B + 128B
        dst[lane] = __floats2half2_rn(tile[2 * lane][v] * inv,
                                      tile[2 * lane + 1][v] * inv);
        dst[lane + 32] = __floats2half2_rn(tile[64 + 2 * lane][v] * inv,
                                           tile[64 + 2 * lane + 1][v] * inv);
    }
}

// ---------------------------------------------------------------------------
// Kernel 2: gather-copy + fp16->fp32 widen. Warp handles TOK_PER_WARP tokens;
// lane l loads uint2 (4 halves) #l of the row (warp = 256B coalesced read),
// widens to float4, stores 512B coalesced with evict-first so the output
// stream doesn't evict the table from L2.
// ---------------------------------------------------------------------------
#define TOK_PER_WARP 8

__global__ __launch_bounds__(256) void gather_kernel(
        const int* __restrict__ x,
        float* __restrict__ out,
        int n_tok) {
    const int gwarp = (blockIdx.x * blockDim.x + threadIdx.x) >> 5;
    const int lane  = threadIdx.x & 31;
    const int t0    = gwarp * TOK_PER_WARP;
    if (t0 >= n_tok) return;

    if (t0 + TOK_PER_WARP <= n_tok) {
        int idx[TOK_PER_WARP];
        #pragma unroll
        for (int r = 0; r < TOK_PER_WARP; r++)
            idx[r] = __ldg(&x[t0 + r]);

        uint2 h[TOK_PER_WARP];
        #pragma unroll
        for (int r = 0; r < TOK_PER_WARP; r++)
            h[r] = __ldg(reinterpret_cast<const uint2*>(
                       g_table + (size_t)idx[r] * EMB) + lane);

        #pragma unroll
        for (int r = 0; r < TOK_PER_WARP; r++) {
            float2 f0 = __half22float2(*reinterpret_cast<__half2*>(&h[r].x));
            float2 f1 = __half22float2(*reinterpret_cast<__half2*>(&h[r].y));
            float4 o;
            o.x = f0.x; o.y = f0.y; o.z = f1.x; o.w = f1.y;
            __stcs(reinterpret_cast<float4*>(out + (size_t)(t0 + r) * EMB) + lane, o);
        }
    } else {
        for (int t = t0; t < n_tok; t++) {
            uint2 h = __ldg(reinterpret_cast<const uint2*>(
                          g_table + (size_t)__ldg(&x[t]) * EMB) + lane);
            float2 f0 = __half22float2(*reinterpret_cast<__half2*>(&h.x));
            float2 f1 = __half22float2(*reinterpret_cast<__half2*>(&h.y));
            float4 o;
            o.x = f0.x; o.y = f0.y; o.z = f1.x; o.w = f1.y;
            __stcs(reinterpret_cast<float4*>(out + (size_t)t * EMB) + lane, o);
        }
    }
}

// ---------------------------------------------------------------------------
extern "C" void kernel_launch(void* const* d_in, const int* in_sizes, int n_in,
                              void* d_out, int out_size) {
    const int*   x = (const int*)d_in[0];    // [4096, 200] int32
    const float* W = (const float*)d_in[1];  // [128, 100000] fp32
    const float* b = (const float*)d_in[2];  // [128] fp32
    float* out = (float*)d_out;              // [4096, 200, 128] fp32

    const int n_tok = in_sizes[0];           // 819200

    build_table_kernel<<<VOCAB / 32, 256>>>(W, b);

    const int warps_needed = (n_tok + TOK_PER_WARP - 1) / TOK_PER_WARP;
    const int blocks = (warps_needed + 7) / 8;   // 8 warps per 256-thread block
    gather_kernel<<<blocks, 256>>>(x, out, n_tok);
}